// round 14
// baseline (speedup 1.0000x reference)
#include <cuda_runtime.h>
#include <cuda_bf16.h>

#define BATCH 16
#define NPTS  2048
#define CH    128
#define MROWS (BATCH * NPTS)   // 32768
#define KNN_K 7                // neighbors excluding self

#define ALPHA_C ((float)(8.0 / 9.0))
#define IA8_C   ((float)((1.0 - 8.0 / 9.0) / 8.0))

// ---------------- scratch (device globals; no allocation allowed) ----------
__device__ float g_pts[(size_t)MROWS * CH];
__device__ float g_Hg [(size_t)MROWS * CH];
__device__ int   g_nbr[(size_t)MROWS * KNN_K];
__device__ float g_UV [(size_t)MROWS * 12];
__device__ __nv_bfloat16 g_Xhi[(size_t)MROWS * CH];
__device__ __nv_bfloat16 g_Xlo[(size_t)MROWS * CH];
__device__ __nv_bfloat16 g_Rhi[(size_t)MROWS * CH];
__device__ __nv_bfloat16 g_Rlo[(size_t)MROWS * CH];
__device__ __nv_bfloat16 g_Wch[4 * CH * CH];
__device__ __nv_bfloat16 g_Wcl[4 * CH * CH];
__device__ __nv_bfloat16 g_Wgh[4 * CH * CH];
__device__ __nv_bfloat16 g_Wgl[4 * CH * CH];

// ---------------- bf16 hi/lo split helpers ----------------------------------
__device__ __forceinline__ void split1(float v, __nv_bfloat16& h, __nv_bfloat16& l) {
    h = __float2bfloat16(v);
    l = __float2bfloat16(v - __bfloat162float(h));
}

__device__ __forceinline__ void split_store4(float4 v, __nv_bfloat16* hi,
                                             __nv_bfloat16* lo, size_t off) {
    __nv_bfloat16 h0, h1, h2, h3, l0, l1, l2, l3;
    split1(v.x, h0, l0); split1(v.y, h1, l1);
    split1(v.z, h2, l2); split1(v.w, h3, l3);
    __nv_bfloat162 a; a.x = h0; a.y = h1;
    __nv_bfloat162 b; b.x = h2; b.y = h3;
    *(__nv_bfloat162*)(hi + off)     = a;
    *(__nv_bfloat162*)(hi + off + 2) = b;
    __nv_bfloat162 c; c.x = l0; c.y = l1;
    __nv_bfloat162 d; d.x = l2; d.y = l3;
    *(__nv_bfloat162*)(lo + off)     = c;
    *(__nv_bfloat162*)(lo + off + 2) = d;
}

// ---------------- warp MMA / async-copy helpers -----------------------------
__device__ __forceinline__ unsigned smem_u32(const void* p) {
    unsigned a;
    asm("{ .reg .u64 t; cvta.to.shared.u64 t, %1; cvt.u32.u64 %0, t; }"
        : "=r"(a) : "l"(p));
    return a;
}

__device__ __forceinline__ void ldsm_x4(unsigned addr, unsigned& r0, unsigned& r1,
                                        unsigned& r2, unsigned& r3) {
    asm volatile("ldmatrix.sync.aligned.m8n8.x4.shared.b16 {%0,%1,%2,%3}, [%4];"
                 : "=r"(r0), "=r"(r1), "=r"(r2), "=r"(r3) : "r"(addr));
}

__device__ __forceinline__ void mma_bf16(float* c, const unsigned* a,
                                         unsigned b0, unsigned b1) {
    asm volatile(
        "mma.sync.aligned.m16n8k16.row.col.f32.bf16.bf16.f32 "
        "{%0,%1,%2,%3}, {%4,%5,%6,%7}, {%8,%9}, {%0,%1,%2,%3};"
        : "+f"(c[0]), "+f"(c[1]), "+f"(c[2]), "+f"(c[3])
        : "r"(a[0]), "r"(a[1]), "r"(a[2]), "r"(a[3]), "r"(b0), "r"(b1));
}

__device__ __forceinline__ void cp16(unsigned saddr, const void* gptr) {
    asm volatile("cp.async.cg.shared.global [%0], [%1], 16;"
                 :: "r"(saddr), "l"(gptr) : "memory");
}
#define CP_COMMIT() asm volatile("cp.async.commit_group;" ::: "memory")
#define CP_WAIT0()  asm volatile("cp.async.wait_group 0;" ::: "memory")
#define CP_WAIT1()  asm volatile("cp.async.wait_group 1;" ::: "memory")

// swizzled smem offset of 8-bf16 granule at (row, col): 128x128 bf16 tile,
// row stride 256B, 16B granules XOR-swizzled by row&7 -> conflict-free ldmatrix.
__device__ __forceinline__ unsigned sw_addr(unsigned base, int row, int col) {
    int g = (col >> 3) ^ (row & 7);
    return base + (unsigned)row * 256u + (unsigned)g * 16u;
}

// per-lane ldmatrix.x4 address for a 16x16 tile at (rbase, kbase)
__device__ __forceinline__ unsigned tile_addr(unsigned base, int rbase, int kbase, int lane) {
    int r = rbase + (lane & 7) + ((lane >> 3) & 1) * 8;
    int c = kbase + (lane >> 4) * 8;
    return sw_addr(base, r, c);
}

// async-stage one 128x128 bf16 tile into swizzled smem (512-thread version)
__device__ __forceinline__ void stage_tile(unsigned sdst, const __nv_bfloat16* gsrc,
                                           int tid) {
    #pragma unroll
    for (int it = 0; it < 4; it++) {
        int idx = it * 512 + tid;          // [0, 2048) 16B granules
        int row = idx >> 4;
        int g   = idx & 15;
        unsigned off = (unsigned)row * 256u + (unsigned)((g ^ (row & 7)) * 16);
        cp16(sdst + off, gsrc + (size_t)row * CH + g * 8);
    }
}

// ---------------- transpose (B,C,N) -> (B,N,C) + bf16 splits ---------------
__global__ __launch_bounds__(256) void transpose_in_kernel(const float* __restrict__ src)
{
    __shared__ float tile[32][33];
    int b  = blockIdx.z;
    int c0 = blockIdx.y * 32;
    int n0 = blockIdx.x * 32;
    int tx = threadIdx.x, ty = threadIdx.y;
    #pragma unroll
    for (int r = ty; r < 32; r += 8)
        tile[r][tx] = src[((size_t)b * CH + c0 + r) * NPTS + n0 + tx];
    __syncthreads();
    #pragma unroll
    for (int r = ty; r < 32; r += 8) {
        float v = tile[tx][r];
        size_t o = ((size_t)b * NPTS + n0 + r) * CH + c0 + tx;
        g_pts[o] = v;
        __nv_bfloat16 h, l;
        split1(v, h, l);
        g_Xhi[o] = h; g_Xlo[o] = l;
        float rv = fmaxf(v, 0.0f);
        split1(rv, h, l);
        g_Rhi[o] = h; g_Rlo[o] = l;
    }
}

// ---------------- transpose (B,N,C) -> (B,C,N) into output -----------------
__global__ __launch_bounds__(256) void transpose_out_kernel(float* __restrict__ dst)
{
    __shared__ float tile[32][33];
    int b  = blockIdx.z;
    int c0 = blockIdx.y * 32;
    int n0 = blockIdx.x * 32;
    int tx = threadIdx.x, ty = threadIdx.y;
    #pragma unroll
    for (int r = ty; r < 32; r += 8)
        tile[r][tx] = g_pts[((size_t)b * NPTS + n0 + r) * CH + c0 + tx];
    __syncthreads();
    #pragma unroll
    for (int r = ty; r < 32; r += 8)
        dst[((size_t)b * CH + c0 + r) * NPTS + n0 + tx] = tile[tx][r];
}

// ---------------- weight split: fp32 -> bf16 hi/lo -------------------------
__global__ __launch_bounds__(256) void wsplit_kernel(const float* __restrict__ Wc,
                                                     const float* __restrict__ Wg)
{
    int i = blockIdx.x * 256 + threadIdx.x;   // [0, 65536)
    __nv_bfloat16 h, l;
    split1(Wc[i], h, l); g_Wch[i] = h; g_Wcl[i] = l;
    split1(Wg[i], h, l); g_Wgh[i] = h; g_Wgl[i] = l;
}

// ---------------- KNN: 7 nearest neighbors (excluding self) ----------------
__global__ __launch_bounds__(128) void knn_kernel(const float* __restrict__ xyz)
{
    __shared__ float sx[NPTS], sy[NPTS], sz[NPTS], s2[NPTS];
    int b = blockIdx.y;
    const float* base = xyz + (size_t)b * 3 * NPTS;
    for (int j = threadIdx.x; j < NPTS; j += 128) {
        float x = base[j], y = base[NPTS + j], z = base[2 * NPTS + j];
        sx[j] = x; sy[j] = y; sz[j] = z;
        s2[j] = x * x + y * y + z * z;
    }
    __syncthreads();

    int i = blockIdx.x * 128 + threadIdx.x;
    float xi = sx[i], yi = sy[i], zi = sz[i], x2i = s2[i];

    float d[8];
    int   id[8];
    #pragma unroll
    for (int t = 0; t < 8; t++) { d[t] = 3.0e38f; id[t] = 0; }

    for (int j = 0; j < NPTS; j++) {
        float inner = xi * sx[j] + yi * sy[j] + zi * sz[j];
        float dist  = x2i + s2[j] - 2.0f * inner;
        if (dist < d[7]) {
            #pragma unroll
            for (int s = 7; s >= 1; --s) {
                if      (dist < d[s - 1]) { d[s] = d[s - 1]; id[s] = id[s - 1]; }
                else if (dist < d[s])     { d[s] = dist;     id[s] = j; }
            }
            if (dist < d[0]) { d[0] = dist; id[0] = j; }
        }
    }
    int* out = g_nbr + (size_t)(b * NPTS + i) * KNN_K;
    #pragma unroll
    for (int t = 0; t < KNN_K; t++) out[t] = id[t + 1];
}

// ---------------- HMMA bf16x3 GEMM, persistent + pipelined, 16 warps -------
// y=0: Hc = relu(X)@Wc^T -> g_pts += (8/9)*Hc (in place)
// y=1: Hg = X@Wg^T       -> g_Hg
// Grid (74, 2): one CTA per SM. B (hi+lo) resident in smem; A tiles stream
// through 2 stages via cp.async. 16 warps in 4(M)x4(N); warp tile 32x32.
#define GRID_X   74
#define NTILES   (MROWS / 128)   // 256
#define SM_B_HI  0
#define SM_B_LO  32768
#define SM_A(st) (65536 + (st) * 65536)   // each stage: hi at +0, lo at +32768
#define GEMM_SMEM (65536 + 2 * 65536)     // 196608

__global__ __launch_bounds__(512, 1) void gemm_kernel(int iter)
{
    extern __shared__ __align__(1024) unsigned char smem[];
    unsigned sbase = smem_u32(smem);
    int tid  = threadIdx.x;
    int lane = tid & 31;
    int wid  = tid >> 5;
    int mw   = wid & 3;    // M warp (0-3)
    int nw   = wid >> 2;   // N warp (0-3)
    bool reluPath = (blockIdx.y == 0);

    const __nv_bfloat16* __restrict__ Ah = reluPath ? g_Rhi : g_Xhi;
    const __nv_bfloat16* __restrict__ Al = reluPath ? g_Rlo : g_Xlo;
    const __nv_bfloat16* __restrict__ Bh = (reluPath ? g_Wch : g_Wgh) + (size_t)iter * CH * CH;
    const __nv_bfloat16* __restrict__ Bl = (reluPath ? g_Wcl : g_Wgl) + (size_t)iter * CH * CH;

    // Prologue: B (resident) + first A tile into stage 0, one async group.
    int t0 = blockIdx.x;               // first tile index for this CTA
    stage_tile(sbase + SM_B_HI, Bh, tid);
    stage_tile(sbase + SM_B_LO, Bl, tid);
    stage_tile(sbase + SM_A(0),         Ah + (size_t)t0 * 128 * CH, tid);
    stage_tile(sbase + SM_A(0) + 32768, Al + (size_t)t0 * 128 * CH, tid);
    CP_COMMIT();

    int buf = 0;
    for (int t = t0; t < NTILES; t += GRID_X, buf ^= 1) {
        int tn = t + GRID_X;
        if (tn < NTILES) {
            stage_tile(sbase + SM_A(buf ^ 1),         Ah + (size_t)tn * 128 * CH, tid);
            stage_tile(sbase + SM_A(buf ^ 1) + 32768, Al + (size_t)tn * 128 * CH, tid);
            CP_COMMIT();
            CP_WAIT1();
        } else {
            CP_WAIT0();
        }
        __syncthreads();

        unsigned abase = sbase + SM_A(buf);
        int m0 = t * 128;

        float acc[2][4][4];
        #pragma unroll
        for (int mt = 0; mt < 2; mt++)
            #pragma unroll
            for (int nt = 0; nt < 4; nt++)
                #pragma unroll
                for (int e = 0; e < 4; e++) acc[mt][nt][e] = 0.0f;

        #pragma unroll
        for (int kk = 0; kk < 8; kk++) {
            int kb = kk * 16;
            unsigned ah[2][4], al[2][4];
            #pragma unroll
            for (int mt = 0; mt < 2; mt++) {
                int rb = mw * 32 + mt * 16;
                ldsm_x4(tile_addr(abase, rb, kb, lane),
                        ah[mt][0], ah[mt][1], ah[mt][2], ah[mt][3]);
                ldsm_x4(tile_addr(abase + 32768, rb, kb, lane),
                        al[mt][0], al[mt][1], al[mt][2], al[mt][3]);
            }
            unsigned bh[2][4], bl[2][4];
            #pragma unroll
            for (int p = 0; p < 2; p++) {
                int nb = nw * 32 + p * 16;
                ldsm_x4(tile_addr(sbase + SM_B_HI, nb, kb, lane),
                        bh[p][0], bh[p][1], bh[p][2], bh[p][3]);
                ldsm_x4(tile_addr(sbase + SM_B_LO, nb, kb, lane),
                        bl[p][0], bl[p][1], bl[p][2], bl[p][3]);
            }
            #pragma unroll
            for (int mt = 0; mt < 2; mt++) {
                #pragma unroll
                for (int nt = 0; nt < 4; nt++) {
                    int p = nt >> 1, h = nt & 1;
                    mma_bf16(acc[mt][nt], ah[mt], bh[p][h], bh[p][h + 2]);
                    mma_bf16(acc[mt][nt], ah[mt], bl[p][h], bl[p][h + 2]);
                    mma_bf16(acc[mt][nt], al[mt], bh[p][h], bh[p][h + 2]);
                }
            }
        }

        // Epilogue
        #pragma unroll
        for (int mt = 0; mt < 2; mt++) {
            #pragma unroll
            for (int nt = 0; nt < 4; nt++) {
                int r0 = m0 + mw * 32 + mt * 16 + (lane >> 2);
                int c  = nw * 32 + nt * 8 + (lane & 3) * 2;
                float* p0 = (reluPath ? g_pts : g_Hg) + (size_t)r0 * CH + c;
                float* p1 = p0 + 8 * CH;
                if (reluPath) {
                    float2 v0 = *(float2*)p0, v1 = *(float2*)p1;
                    v0.x += ALPHA_C * acc[mt][nt][0];
                    v0.y += ALPHA_C * acc[mt][nt][1];
                    v1.x += ALPHA_C * acc[mt][nt][2];
                    v1.y += ALPHA_C * acc[mt][nt][3];
                    *(float2*)p0 = v0;
                    *(float2*)p1 = v1;
                } else {
                    *(float2*)p0 = make_float2(acc[mt][nt][0], acc[mt][nt][1]);
                    *(float2*)p1 = make_float2(acc[mt][nt][2], acc[mt][nt][3]);
                }
            }
        }
        __syncthreads();
    }
}

// ---------------- combine: pts += IA8*(Hg self + 7 nbrs); emit bf16 splits -
__global__ __launch_bounds__(256) void combine_kernel(int emit)
{
    int row  = blockIdx.x * 8 + (threadIdx.x >> 5);
    int lane = threadIdx.x & 31;
    int bbase = row & ~(NPTS - 1);

    const int* nb = g_nbr + (size_t)row * KNN_K;
    int j[KNN_K];
    #pragma unroll
    for (int t = 0; t < KNN_K; t++) j[t] = bbase + nb[t];

    size_t roff = (size_t)row * CH + lane * 4;
    float4 g = *(const float4*)(g_Hg + roff);
    #pragma unroll
    for (int t = 0; t < KNN_K; t++) {
        float4 v = *(const float4*)(g_Hg + (size_t)j[t] * CH + lane * 4);
        g.x += v.x; g.y += v.y; g.z += v.z; g.w += v.w;
    }
    float4 p = *(const float4*)(g_pts + roff);  // already has shortcut + A*Hc
    p.x += IA8_C * g.x;
    p.y += IA8_C * g.y;
    p.z += IA8_C * g.z;
    p.w += IA8_C * g.w;
    *(float4*)(g_pts + roff) = p;

    if (emit) {
        split_store4(p, g_Xhi, g_Xlo, roff);
        float4 r = make_float4(fmaxf(p.x, 0.0f), fmaxf(p.y, 0.0f),
                               fmaxf(p.z, 0.0f), fmaxf(p.w, 0.0f));
        split_store4(r, g_Rhi, g_Rlo, roff);
    }
}

// ---------------- U = pts@Wuc^T, V = pts@Wug^T -----------------------------
__global__ __launch_bounds__(128) void uv_kernel(
    const float* __restrict__ Wuc, const float* __restrict__ Wug)
{
    __shared__ float w[12][128];
    int tid = threadIdx.x;
    for (int t = tid; t < 768; t += 128) w[t >> 7][t & 127]       = Wuc[t];
    for (int t = tid; t < 768; t += 128) w[6 + (t >> 7)][t & 127] = Wug[t];
    __syncthreads();

    int row  = blockIdx.x * 4 + (tid >> 5);
    int lane = tid & 31;
    float4 p = *(const float4*)(g_pts + (size_t)row * CH + lane * 4);

    float r[12];
    #pragma unroll
    for (int o = 0; o < 12; o++) {
        float4 wv = *(const float4*)&w[o][lane * 4];
        r[o] = p.x * wv.x + p.y * wv.y + p.z * wv.z + p.w * wv.w;
    }
    #pragma unroll
    for (int o = 0; o < 12; o++) {
        #pragma unroll
        for (int s = 16; s > 0; s >>= 1)
            r[o] += __shfl_xor_sync(0xffffffff, r[o], s);
    }
    if (lane == 0) {
        float* out = g_UV + (size_t)row * 12;
        #pragma unroll
        for (int o = 0; o < 12; o++) out[o] = r[o];
    }
}

// ---------------- final: new_xyz = combine + unpool reshape ----------------
__global__ __launch_bounds__(256) void final_kernel(
    const float* __restrict__ xyz, float* __restrict__ out)
{
    int row = blockIdx.x * 256 + threadIdx.x;   // [0, 32768)
    int b = row >> 11, n = row & (NPTS - 1);
    int bbase = b << 11;

    const float* uv = g_UV + (size_t)row * 12;
    float nv[6];
    #pragma unroll
    for (int o = 0; o < 6; o++) nv[o] = uv[6 + o];

    const int* nb = g_nbr + (size_t)row * KNN_K;
    #pragma unroll
    for (int t = 0; t < KNN_K; t++) {
        const float* v = g_UV + (size_t)(bbase + nb[t]) * 12 + 6;
        #pragma unroll
        for (int o = 0; o < 6; o++) nv[o] += v[o];
    }

    #pragma unroll
    for (int c = 0; c < 3; c++) {
        float base = xyz[(size_t)b * 3 * NPTS + c * NPTS + n];
        #pragma unroll
        for (int p = 0; p < 2; p++) {
            float val = ALPHA_C * uv[2 * c + p] + IA8_C * nv[2 * c + p] + base;
            out[(size_t)b * 3 * 2 * NPTS + c * 2 * NPTS + p * NPTS + n] = val;
        }
    }
}

// ---------------------------------------------------------------------------
extern "C" void kernel_launch(void* const* d_in, const int* in_sizes, int n_in,
                              void* d_out, int out_size)
{
    const float* xyz    = (const float*)d_in[0];   // (16, 3, 2048)
    const float* points = (const float*)d_in[1];   // (16, 128, 2048)
    const float* Wc     = (const float*)d_in[2];   // (4, 128, 128)
    const float* Wg     = (const float*)d_in[3];   // (4, 128, 128)
    const float* Wuc    = (const float*)d_in[4];   // (6, 128)
    const float* Wug    = (const float*)d_in[5];   // (6, 128)
    float* out = (float*)d_out;                    // [new_xyz | pts^T]

    cudaFuncSetAttribute(gemm_kernel, cudaFuncAttributeMaxDynamicSharedMemorySize,
                         GEMM_SMEM);

    dim3 tposGrid(NPTS / 32, CH / 32, BATCH);
    dim3 tposBlk(32, 8);

    transpose_in_kernel<<<tposGrid, tposBlk>>>(points);
    knn_kernel<<<dim3(NPTS / 128, BATCH), 128>>>(xyz);
    wsplit_kernel<<<256, 256>>>(Wc, Wg);

    for (int i = 0; i < 4; i++) {
        gemm_kernel<<<dim3(GRID_X, 2), 512, GEMM_SMEM>>>(i);
        combine_kernel<<<MROWS / 8, 256>>>(i < 3 ? 1 : 0);
    }

    uv_kernel<<<MROWS / 4, 128>>>(Wuc, Wug);
    final_kernel<<<MROWS / 256, 256>>>(xyz, out);
    transpose_out_kernel<<<tposGrid, tposBlk>>>(out + (size_t)BATCH * 3 * 2 * NPTS);
}

// round 16
// speedup vs baseline: 1.0262x; 1.0262x over previous
#include <cuda_runtime.h>
#include <cuda_bf16.h>

#define BATCH 16
#define NPTS  2048
#define CH    128
#define MROWS (BATCH * NPTS)   // 32768
#define KNN_K 7                // neighbors excluding self

#define ALPHA_C ((float)(8.0 / 9.0))
#define IA8_C   ((float)((1.0 - 8.0 / 9.0) / 8.0))

// ---------------- scratch (device globals; no allocation allowed) ----------
__device__ float g_pts[(size_t)MROWS * CH];
__device__ float g_Hg [(size_t)MROWS * CH];
__device__ int   g_nbr[(size_t)MROWS * KNN_K];
__device__ float g_UV [(size_t)MROWS * 12];
__device__ __nv_bfloat16 g_Xhi[(size_t)MROWS * CH];
__device__ __nv_bfloat16 g_Xlo[(size_t)MROWS * CH];
__device__ __nv_bfloat16 g_Wch[4 * CH * CH];
__device__ __nv_bfloat16 g_Wcl[4 * CH * CH];
__device__ __nv_bfloat16 g_Wgh[4 * CH * CH];
__device__ __nv_bfloat16 g_Wgl[4 * CH * CH];

// ---------------- bf16 hi/lo split helpers ----------------------------------
__device__ __forceinline__ void split1(float v, __nv_bfloat16& h, __nv_bfloat16& l) {
    h = __float2bfloat16(v);
    l = __float2bfloat16(v - __bfloat162float(h));
}

__device__ __forceinline__ void split_store4(float4 v, __nv_bfloat16* hi,
                                             __nv_bfloat16* lo, size_t off) {
    __nv_bfloat16 h0, h1, h2, h3, l0, l1, l2, l3;
    split1(v.x, h0, l0); split1(v.y, h1, l1);
    split1(v.z, h2, l2); split1(v.w, h3, l3);
    __nv_bfloat162 a; a.x = h0; a.y = h1;
    __nv_bfloat162 b; b.x = h2; b.y = h3;
    *(__nv_bfloat162*)(hi + off)     = a;
    *(__nv_bfloat162*)(hi + off + 2) = b;
    __nv_bfloat162 c; c.x = l0; c.y = l1;
    __nv_bfloat162 d; d.x = l2; d.y = l3;
    *(__nv_bfloat162*)(lo + off)     = c;
    *(__nv_bfloat162*)(lo + off + 2) = d;
}

// ---------------- warp MMA / async-copy helpers -----------------------------
__device__ __forceinline__ unsigned smem_u32(const void* p) {
    unsigned a;
    asm("{ .reg .u64 t; cvta.to.shared.u64 t, %1; cvt.u32.u64 %0, t; }"
        : "=r"(a) : "l"(p));
    return a;
}

__device__ __forceinline__ void ldsm_x4(unsigned addr, unsigned& r0, unsigned& r1,
                                        unsigned& r2, unsigned& r3) {
    asm volatile("ldmatrix.sync.aligned.m8n8.x4.shared.b16 {%0,%1,%2,%3}, [%4];"
                 : "=r"(r0), "=r"(r1), "=r"(r2), "=r"(r3) : "r"(addr));
}

__device__ __forceinline__ void mma_bf16(float* c, const unsigned* a,
                                         unsigned b0, unsigned b1) {
    asm volatile(
        "mma.sync.aligned.m16n8k16.row.col.f32.bf16.bf16.f32 "
        "{%0,%1,%2,%3}, {%4,%5,%6,%7}, {%8,%9}, {%0,%1,%2,%3};"
        : "+f"(c[0]), "+f"(c[1]), "+f"(c[2]), "+f"(c[3])
        : "r"(a[0]), "r"(a[1]), "r"(a[2]), "r"(a[3]), "r"(b0), "r"(b1));
}

__device__ __forceinline__ void cp16(unsigned saddr, const void* gptr) {
    asm volatile("cp.async.cg.shared.global [%0], [%1], 16;"
                 :: "r"(saddr), "l"(gptr) : "memory");
}
#define CP_COMMIT() asm volatile("cp.async.commit_group;" ::: "memory")
#define CP_WAIT0()  asm volatile("cp.async.wait_group 0;" ::: "memory")

// swizzled smem offset of 8-bf16 granule at (row, col): 128x128 bf16 tile,
// row stride 256B, 16B granules XOR-swizzled by row&7 -> conflict-free ldmatrix.
__device__ __forceinline__ unsigned sw_addr(unsigned base, int row, int col) {
    int g = (col >> 3) ^ (row & 7);
    return base + (unsigned)row * 256u + (unsigned)g * 16u;
}

// per-lane ldmatrix.x4 address for a 16x16 tile at (rbase, kbase)
__device__ __forceinline__ unsigned tile_addr(unsigned base, int rbase, int kbase, int lane) {
    int r = rbase + (lane & 7) + ((lane >> 3) & 1) * 8;
    int c = kbase + (lane >> 4) * 8;
    return sw_addr(base, r, c);
}

// async-stage one 128x128 bf16 tile into swizzled smem (256 threads)
__device__ __forceinline__ void stage_tile(unsigned sdst, const __nv_bfloat16* gsrc,
                                           int tid) {
    #pragma unroll
    for (int it = 0; it < 8; it++) {
        int idx = it * 256 + tid;          // [0, 2048) 16B granules
        int row = idx >> 4;
        int g   = idx & 15;
        unsigned off = (unsigned)row * 256u + (unsigned)((g ^ (row & 7)) * 16);
        cp16(sdst + off, gsrc + (size_t)row * CH + g * 8);
    }
}

// derive relu fragments: rh = max(ah, 0); rl = al * (ah > 0)
__device__ __forceinline__ void relu_frags(const unsigned* ah, const unsigned* al,
                                           unsigned* rh, unsigned* rl) {
    __nv_bfloat162 z = __floats2bfloat162_rn(0.0f, 0.0f);
    #pragma unroll
    for (int i = 0; i < 4; i++) {
        __nv_bfloat162 a = *(const __nv_bfloat162*)&ah[i];
        __nv_bfloat162 l = *(const __nv_bfloat162*)&al[i];
        __nv_bfloat162 h = __hmax2(a, z);
        __nv_bfloat162 m = __hgt2(a, z);      // exact 1.0 / 0.0 per lane
        __nv_bfloat162 lr = __hmul2(l, m);    // *1.0 or *0.0: exact
        rh[i] = *(const unsigned*)&h;
        rl[i] = *(const unsigned*)&lr;
    }
}

// ---------------- transpose (B,C,N) -> (B,N,C) + bf16 splits ---------------
__global__ __launch_bounds__(256) void transpose_in_kernel(const float* __restrict__ src)
{
    __shared__ float tile[32][33];
    int b  = blockIdx.z;
    int c0 = blockIdx.y * 32;
    int n0 = blockIdx.x * 32;
    int tx = threadIdx.x, ty = threadIdx.y;
    #pragma unroll
    for (int r = ty; r < 32; r += 8)
        tile[r][tx] = src[((size_t)b * CH + c0 + r) * NPTS + n0 + tx];
    __syncthreads();
    #pragma unroll
    for (int r = ty; r < 32; r += 8) {
        float v = tile[tx][r];
        size_t o = ((size_t)b * NPTS + n0 + r) * CH + c0 + tx;
        g_pts[o] = v;
        __nv_bfloat16 h, l;
        split1(v, h, l);
        g_Xhi[o] = h; g_Xlo[o] = l;
    }
}

// ---------------- transpose (B,N,C) -> (B,C,N) into output -----------------
__global__ __launch_bounds__(256) void transpose_out_kernel(float* __restrict__ dst)
{
    __shared__ float tile[32][33];
    int b  = blockIdx.z;
    int c0 = blockIdx.y * 32;
    int n0 = blockIdx.x * 32;
    int tx = threadIdx.x, ty = threadIdx.y;
    #pragma unroll
    for (int r = ty; r < 32; r += 8)
        tile[r][tx] = g_pts[((size_t)b * NPTS + n0 + r) * CH + c0 + tx];
    __syncthreads();
    #pragma unroll
    for (int r = ty; r < 32; r += 8)
        dst[((size_t)b * CH + c0 + r) * NPTS + n0 + tx] = tile[tx][r];
}

// ---------------- weight split: fp32 -> bf16 hi/lo -------------------------
__global__ __launch_bounds__(256) void wsplit_kernel(const float* __restrict__ Wc,
                                                     const float* __restrict__ Wg)
{
    int i = blockIdx.x * 256 + threadIdx.x;   // [0, 65536)
    __nv_bfloat16 h, l;
    split1(Wc[i], h, l); g_Wch[i] = h; g_Wcl[i] = l;
    split1(Wg[i], h, l); g_Wgh[i] = h; g_Wgl[i] = l;
}

// ---------------- KNN: 7 nearest neighbors (excluding self) ----------------
__global__ __launch_bounds__(128) void knn_kernel(const float* __restrict__ xyz)
{
    __shared__ float sx[NPTS], sy[NPTS], sz[NPTS], s2[NPTS];
    int b = blockIdx.y;
    const float* base = xyz + (size_t)b * 3 * NPTS;
    for (int j = threadIdx.x; j < NPTS; j += 128) {
        float x = base[j], y = base[NPTS + j], z = base[2 * NPTS + j];
        sx[j] = x; sy[j] = y; sz[j] = z;
        s2[j] = x * x + y * y + z * z;
    }
    __syncthreads();

    int i = blockIdx.x * 128 + threadIdx.x;
    float xi = sx[i], yi = sy[i], zi = sz[i], x2i = s2[i];

    float d[8];
    int   id[8];
    #pragma unroll
    for (int t = 0; t < 8; t++) { d[t] = 3.0e38f; id[t] = 0; }

    for (int j = 0; j < NPTS; j++) {
        float inner = xi * sx[j] + yi * sy[j] + zi * sz[j];
        float dist  = x2i + s2[j] - 2.0f * inner;
        if (dist < d[7]) {
            #pragma unroll
            for (int s = 7; s >= 1; --s) {
                if      (dist < d[s - 1]) { d[s] = d[s - 1]; id[s] = id[s - 1]; }
                else if (dist < d[s])     { d[s] = dist;     id[s] = j; }
            }
            if (dist < d[0]) { d[0] = dist; id[0] = j; }
        }
    }
    int* out = g_nbr + (size_t)(b * NPTS + i) * KNN_K;
    #pragma unroll
    for (int t = 0; t < KNN_K; t++) out[t] = id[t + 1];
}

// ---------------- fused dual-output HMMA bf16x3 GEMM -----------------------
// One kernel computes BOTH per iteration:
//   Hc = relu(X)@Wc^T -> g_pts += (8/9)*Hc (in place)   [relu frags derived]
//   Hg = X@Wg^T       -> g_Hg
// Grid (148): persistent, tiles t = bx, bx+148. B (4 x 32KB) resident.
// A: Xhi double-buffered (H0/H1), Xlo single slot (L). 8 warps 4(M)x2(N),
// warp tile 32x64, dual accumulators.
#define NTILES   (MROWS / 128)   // 256
#define GSM_B    0               // Wch@0 Wcl@32768 Wgh@65536 Wgl@98304
#define GSM_H0   131072
#define GSM_H1   163840
#define GSM_L    196608
#define GEMM_SMEM 229376

__global__ __launch_bounds__(256, 1) void gemm_fused_kernel(int iter)
{
    extern __shared__ __align__(1024) unsigned char smem[];
    unsigned sbase = smem_u32(smem);
    int tid  = threadIdx.x;
    int lane = tid & 31;
    int wid  = tid >> 5;
    int mw   = wid & 3;    // M warp (0-3)
    int nw   = wid >> 2;   // N warp (0-1)

    const __nv_bfloat16* __restrict__ Wch = g_Wch + (size_t)iter * CH * CH;
    const __nv_bfloat16* __restrict__ Wcl = g_Wcl + (size_t)iter * CH * CH;
    const __nv_bfloat16* __restrict__ Wgh = g_Wgh + (size_t)iter * CH * CH;
    const __nv_bfloat16* __restrict__ Wgl = g_Wgl + (size_t)iter * CH * CH;

    int t0   = blockIdx.x;
    bool has2 = (t0 + 148) < NTILES;

    // Prologue: B (resident) + first A tile.
    stage_tile(sbase + GSM_B,          Wch, tid);
    stage_tile(sbase + GSM_B + 32768,  Wcl, tid);
    stage_tile(sbase + GSM_B + 65536,  Wgh, tid);
    stage_tile(sbase + GSM_B + 98304,  Wgl, tid);
    stage_tile(sbase + GSM_H0, g_Xhi + (size_t)t0 * 128 * CH, tid);
    stage_tile(sbase + GSM_L,  g_Xlo + (size_t)t0 * 128 * CH, tid);
    CP_COMMIT();
    CP_WAIT0();
    __syncthreads();

    // Prefetch tile2's hi half (overlaps tile1 compute).
    if (has2) {
        stage_tile(sbase + GSM_H1, g_Xhi + (size_t)(t0 + 148) * 128 * CH, tid);
        CP_COMMIT();
    }

    #pragma unroll 1
    for (int it2 = 0; it2 < 2; it2++) {
        if (it2 == 1 && !has2) break;
        if (it2 == 1) {
            // reload lo slot for tile2 (hi already in flight/arrived)
            stage_tile(sbase + GSM_L, g_Xlo + (size_t)(t0 + 148) * 128 * CH, tid);
            CP_COMMIT();
            CP_WAIT0();
            __syncthreads();
        }
        unsigned abh = sbase + (it2 ? GSM_H1 : GSM_H0);
        unsigned abl = sbase + GSM_L;
        int m0 = (t0 + it2 * 148) * 128;

        float accC[2][8][4], accG[2][8][4];
        #pragma unroll
        for (int mt = 0; mt < 2; mt++)
            #pragma unroll
            for (int nt = 0; nt < 8; nt++)
                #pragma unroll
                for (int e = 0; e < 4; e++) { accC[mt][nt][e] = 0.0f; accG[mt][nt][e] = 0.0f; }

        #pragma unroll
        for (int kk = 0; kk < 8; kk++) {
            int kb = kk * 16;
            unsigned ah[2][4], al[2][4], rh[2][4], rl[2][4];
            #pragma unroll
            for (int mt = 0; mt < 2; mt++) {
                int rb = mw * 32 + mt * 16;
                ldsm_x4(tile_addr(abh, rb, kb, lane),
                        ah[mt][0], ah[mt][1], ah[mt][2], ah[mt][3]);
                ldsm_x4(tile_addr(abl, rb, kb, lane),
                        al[mt][0], al[mt][1], al[mt][2], al[mt][3]);
                relu_frags(ah[mt], al[mt], rh[mt], rl[mt]);
            }
            // ---- Hc: relu frags x Wc ----
            {
                unsigned bh[4][4], bl[4][4];
                #pragma unroll
                for (int p = 0; p < 4; p++) {
                    int nb = nw * 64 + p * 16;
                    ldsm_x4(tile_addr(sbase + GSM_B, nb, kb, lane),
                            bh[p][0], bh[p][1], bh[p][2], bh[p][3]);
                    ldsm_x4(tile_addr(sbase + GSM_B + 32768, nb, kb, lane),
                            bl[p][0], bl[p][1], bl[p][2], bl[p][3]);
                }
                #pragma unroll
                for (int mt = 0; mt < 2; mt++)
                    #pragma unroll
                    for (int nt = 0; nt < 8; nt++) {
                        int p = nt >> 1, h = nt & 1;
                        mma_bf16(accC[mt][nt], rh[mt], bh[p][h], bh[p][h + 2]);
                        mma_bf16(accC[mt][nt], rh[mt], bl[p][h], bl[p][h + 2]);
                        mma_bf16(accC[mt][nt], rl[mt], bh[p][h], bh[p][h + 2]);
                    }
            }
            // ---- Hg: X frags x Wg ----
            {
                unsigned bh[4][4], bl[4][4];
                #pragma unroll
                for (int p = 0; p < 4; p++) {
                    int nb = nw * 64 + p * 16;
                    ldsm_x4(tile_addr(sbase + GSM_B + 65536, nb, kb, lane),
                            bh[p][0], bh[p][1], bh[p][2], bh[p][3]);
                    ldsm_x4(tile_addr(sbase + GSM_B + 98304, nb, kb, lane),
                            bl[p][0], bl[p][1], bl[p][2], bl[p][3]);
                }
                #pragma unroll
                for (int mt = 0; mt < 2; mt++)
                    #pragma unroll
                    for (int nt = 0; nt < 8; nt++) {
                        int p = nt >> 1, h = nt & 1;
                        mma_bf16(accG[mt][nt], ah[mt], bh[p][h], bh[p][h + 2]);
                        mma_bf16(accG[mt][nt], ah[mt], bl[p][h], bl[p][h + 2]);
                        mma_bf16(accG[mt][nt], al[mt], bh[p][h], bh[p][h + 2]);
                    }
            }
        }

        // Epilogue: g_pts += A*Hc (rmw), g_Hg = Hg
        #pragma unroll
        for (int mt = 0; mt < 2; mt++) {
            #pragma unroll
            for (int nt = 0; nt < 8; nt++) {
                int r0 = m0 + mw * 32 + mt * 16 + (lane >> 2);
                int c  = nw * 64 + nt * 8 + (lane & 3) * 2;
                float* p0 = g_pts + (size_t)r0 * CH + c;
                float* p1 = p0 + 8 * CH;
                float2 v0 = *(float2*)p0, v1 = *(float2*)p1;
                v0.x += ALPHA_C * accC[mt][nt][0];
                v0.y += ALPHA_C * accC[mt][nt][1];
                v1.x += ALPHA_C * accC[mt][nt][2];
                v1.y += ALPHA_C * accC[mt][nt][3];
                *(float2*)p0 = v0;
                *(float2*)p1 = v1;
                float* q0 = g_Hg + (size_t)r0 * CH + c;
                float* q1 = q0 + 8 * CH;
                *(float2*)q0 = make_float2(accG[mt][nt][0], accG[mt][nt][1]);
                *(float2*)q1 = make_float2(accG[mt][nt][2], accG[mt][nt][3]);
            }
        }
        __syncthreads();
    }
}

// ---------------- combine: pts += IA8*(Hg self + 7 nbrs); emit bf16 splits -
__global__ __launch_bounds__(256) void combine_kernel(int emit)
{
    int row  = blockIdx.x * 8 + (threadIdx.x >> 5);
    int lane = threadIdx.x & 31;
    int bbase = row & ~(NPTS - 1);

    const int* nb = g_nbr + (size_t)row * KNN_K;
    int j[KNN_K];
    #pragma unroll
    for (int t = 0; t < KNN_K; t++) j[t] = bbase + nb[t];

    size_t roff = (size_t)row * CH + lane * 4;
    float4 g = *(const float4*)(g_Hg + roff);
    #pragma unroll
    for (int t = 0; t < KNN_K; t++) {
        float4 v = *(const float4*)(g_Hg + (size_t)j[t] * CH + lane * 4);
        g.x += v.x; g.y += v.y; g.z += v.z; g.w += v.w;
    }
    float4 p = *(const float4*)(g_pts + roff);  // already has shortcut + A*Hc
    p.x += IA8_C * g.x;
    p.y += IA8_C * g.y;
    p.z += IA8_C * g.z;
    p.w += IA8_C * g.w;
    *(float4*)(g_pts + roff) = p;

    if (emit) split_store4(p, g_Xhi, g_Xlo, roff);
}

// ---------------- U = pts@Wuc^T, V = pts@Wug^T -----------------------------
__global__ __launch_bounds__(128) void uv_kernel(
    const float* __restrict__ Wuc, const float* __restrict__ Wug)
{
    __shared__ float w[12][128];
    int tid = threadIdx.x;
    for (int t = tid; t < 768; t += 128) w[t >> 7][t & 127]       = Wuc[t];
    for (int t = tid; t < 768; t += 128) w[6 + (t >> 7)][t & 127] = Wug[t];
    __syncthreads();

    int row  = blockIdx.x * 4 + (tid >> 5);
    int lane = tid & 31;
    float4 p = *(const float4*)(g_pts + (size_t)row * CH + lane * 4);

    float r[12];
    #pragma unroll
    for (int o = 0; o < 12; o++) {
        float4 wv = *(const float4*)&w[o][lane * 4];
        r[o] = p.x * wv.x + p.y * wv.y + p.z * wv.z + p.w * wv.w;
    }
    #pragma unroll
    for (int o = 0; o < 12; o++) {
        #pragma unroll
        for (int s = 16; s > 0; s >>= 1)
            r[o] += __shfl_xor_sync(0xffffffff, r[o], s);
    }
    if (lane == 0) {
        float* out = g_UV + (size_t)row * 12;
        #pragma unroll
        for (int o = 0; o < 12; o++) out[o] = r[o];
    }
}

// ---------------- final: new_xyz = combine + unpool reshape ----------------
__global__ __launch_bounds__(256) void final_kernel(
    const float* __restrict__ xyz, float* __restrict__ out)
{
    int row = blockIdx.x * 256 + threadIdx.x;   // [0, 32768)
    int b = row >> 11, n = row & (NPTS - 1);
    int bbase = b << 11;

    const float* uv = g_UV + (size_t)row * 12;
    float nv[6];
    #pragma unroll
    for (int o = 0; o < 6; o++) nv[o] = uv[6 + o];

    const int* nb = g_nbr + (size_t)row * KNN_K;
    #pragma unroll
    for (int t = 0; t < KNN_K; t++) {
        const float* v = g_UV + (size_t)(bbase + nb[t]) * 12 + 6;
        #pragma unroll
        for (int o = 0; o < 6; o++) nv[o] += v[o];
    }

    #pragma unroll
    for (int c = 0; c < 3; c++) {
        float base = xyz[(size_t)b * 3 * NPTS + c * NPTS + n];
        #pragma unroll
        for (int p = 0; p < 2; p++) {
            float val = ALPHA_C * uv[2 * c + p] + IA8_C * nv[2 * c + p] + base;
            out[(size_t)b * 3 * 2 * NPTS + c * 2 * NPTS + p * NPTS + n] = val;
        }
    }
}

// ---------------------------------------------------------------------------
extern "C" void kernel_launch(void* const* d_in, const int* in_sizes, int n_in,
                              void* d_out, int out_size)
{
    const float* xyz    = (const float*)d_in[0];   // (16, 3, 2048)
    const float* points = (const float*)d_in[1];   // (16, 128, 2048)
    const float* Wc     = (const float*)d_in[2];   // (4, 128, 128)
    const float* Wg     = (const float*)d_in[3];   // (4, 128, 128)
    const float* Wuc    = (const float*)d_in[4];   // (6, 128)
    const float* Wug    = (const float*)d_in[5];   // (6, 128)
    float* out = (float*)d_out;                    // [new_xyz | pts^T]

    cudaFuncSetAttribute(gemm_fused_kernel,
                         cudaFuncAttributeMaxDynamicSharedMemorySize, GEMM_SMEM);

    dim3 tposGrid(NPTS / 32, CH / 32, BATCH);
    dim3 tposBlk(32, 8);

    transpose_in_kernel<<<tposGrid, tposBlk>>>(points);
    knn_kernel<<<dim3(NPTS / 128, BATCH), 128>>>(xyz);
    wsplit_kernel<<<256, 256>>>(Wc, Wg);

    for (int i = 0; i < 4; i++) {
        gemm_fused_kernel<<<148, 256, GEMM_SMEM>>>(i);
        combine_kernel<<<MROWS / 8, 256>>>(i < 3 ? 1 : 0);
    }

    uv_kernel<<<MROWS / 4, 128>>>(Wuc, Wug);
    final_kernel<<<MROWS / 256, 256>>>(xyz, out);
    transpose_out_kernel<<<tposGrid, tposBlk>>>(out + (size_t)BATCH * 3 * 2 * NPTS);
}